// round 17
// baseline (speedup 1.0000x reference)
#include <cuda_runtime.h>
#include <cuda_fp16.h>
#include <stdint.h>
#include <math.h>

// Problem constants
#define C_DIM 1536
#define L_Q   2400
#define L_KV  512
#define NH    12
#define HD    128
#define FF_DIM 8960
#define EPS   1e-6f
#define L_PAD 2432

// ---------------- device scratch ----------------
__device__ __align__(256) float g_em[6 * C_DIM];
__device__ __align__(256) float g_q [L_Q * C_DIM];
__device__ __align__(256) float g_s [L_Q * 3 * C_DIM];    // fused-proj fp32 scratch
__device__ __align__(256) float g_b3[3 * C_DIM];
__device__ __align__(256) unsigned short g_hh[L_Q * C_DIM];
__device__ __align__(256) unsigned short g_qh[L_Q * C_DIM];
__device__ __align__(256) unsigned short g_kh[L_Q * C_DIM];
__device__ __align__(256) unsigned short g_vth[C_DIM * L_PAD];
__device__ __align__(256) unsigned short g_yh[L_Q * C_DIM];
__device__ __align__(256) unsigned short g_oh[L_Q * C_DIM];
__device__ __align__(256) unsigned short g_cxh[L_KV * C_DIM];
__device__ __align__(256) unsigned short g_ffh[L_Q * FF_DIM];
__device__ __align__(256) unsigned short g_wA[8 * C_DIM * C_DIM];          // 8 CxC weights^T
__device__ __align__(256) unsigned short g_wF[2 * FF_DIM * C_DIM];         // ffn w1^T, w2^T

// ---------------- helpers ----------------
__device__ __forceinline__ float block_reduce(float v, float* sh, bool is_max) {
    __syncthreads();
    int lane = threadIdx.x & 31, warp = threadIdx.x >> 5;
    #pragma unroll
    for (int o = 16; o > 0; o >>= 1) {
        float other = __shfl_down_sync(0xffffffffu, v, o);
        v = is_max ? fmaxf(v, other) : v + other;
    }
    if (lane == 0) sh[warp] = v;
    __syncthreads();
    int nw = blockDim.x >> 5;
    if (warp == 0) {
        v = (lane < nw) ? sh[lane] : (is_max ? -INFINITY : 0.f);
        #pragma unroll
        for (int o = 16; o > 0; o >>= 1) {
            float other = __shfl_down_sync(0xffffffffu, v, o);
            v = is_max ? fmaxf(v, other) : v + other;
        }
        if (lane == 0) sh[0] = v;
    }
    __syncthreads();
    return sh[0];
}

__device__ __forceinline__ float gelu_tanh(float v) {
    float v3 = v * v * v;
    return 0.5f * v * (1.f + tanhf(0.7978845608028654f * (v + 0.044715f * v3)));
}

// 2^x on the FMA pipe (x <= 0 expected; clamped at -80). rel err ~4e-5.
static __device__ __forceinline__ float fexp2(float x) {
    x = fmaxf(x, -80.f);
    float r  = x + 12582912.f;                 // 1.5 * 2^23 magic round
    float nf = r - 12582912.f;
    float f  = x - nf;                          // [-0.5, 0.5]
    int   n  = __float_as_int(r) - 0x4B400000;  // integer part
    float p = 0.0096181f;
    p = fmaf(p, f, 0.0555041f);
    p = fmaf(p, f, 0.2402265f);
    p = fmaf(p, f, 0.6931472f);
    p = fmaf(p, f, 1.0f);
    return p * __int_as_float((n + 127) << 23);
}

// ---------------- elementwise / norm kernels ----------------
__global__ void em_kernel(const float* __restrict__ e, const float* __restrict__ mod,
                          float* __restrict__ em) {
    int i = blockIdx.x * blockDim.x + threadIdx.x;
    if (i < 6 * C_DIM) em[i] = e[i] + mod[i];
}

__global__ void pack3_kernel(const float* __restrict__ a, const float* __restrict__ b,
                             const float* __restrict__ c, float* __restrict__ d) {
    int i = blockIdx.x * blockDim.x + threadIdx.x;
    if (i < C_DIM) d[i] = a[i];
    else if (i < 2 * C_DIM) d[i] = b[i - C_DIM];
    else if (i < 3 * C_DIM) d[i] = c[i - 2 * C_DIM];
}

__global__ void pack2_kernel(const float* __restrict__ a, const float* __restrict__ b,
                             float* __restrict__ d) {
    int i = blockIdx.x * blockDim.x + threadIdx.x;
    if (i < C_DIM) d[i] = a[i];
    else if (i < 2 * C_DIM) d[i] = b[i - C_DIM];
}

__global__ void zero_pad_kernel(unsigned short* __restrict__ vt) {
    int i = blockIdx.x * blockDim.x + threadIdx.x;
    int r = i >> 5, c = i & 31;
    if (r < C_DIM) vt[(long long)r * L_PAD + L_Q + c] = 0;
}

// LN + modulation -> fp16 hi only
__global__ void ln_mod_split_kernel(const float* __restrict__ x, const float* __restrict__ e0,
                                    const float* __restrict__ e1,
                                    unsigned short* __restrict__ oh) {
    __shared__ float sh[32];
    long long row = blockIdx.x;
    const float* xr = x + row * C_DIM;
    float s = 0.f, s2 = 0.f;
    for (int c = threadIdx.x; c < C_DIM; c += blockDim.x) {
        float v = xr[c];
        s += v; s2 += v * v;
    }
    float S  = block_reduce(s,  sh, false);
    float S2 = block_reduce(s2, sh, false);
    float m   = S  * (1.f / C_DIM);
    float var = S2 * (1.f / C_DIM) - m * m;
    float inv = rsqrtf(var + EPS);
    for (int c = threadIdx.x; c < C_DIM; c += blockDim.x) {
        float v = e0[c] + (xr[c] - m) * inv * (1.f + e1[c]);
        __half hv = __float2half_rn(v);
        oh[row * C_DIM + c] = *reinterpret_cast<unsigned short*>(&hv);
    }
}

__global__ void rms_rope_split_kernel(const float* __restrict__ x, int ldx,
                                      const float* __restrict__ w,
                                      const float* __restrict__ freqs,
                                      unsigned short* __restrict__ dh) {
    __shared__ float sh[32];
    int row = blockIdx.x;
    const float* xr = x + (long long)row * ldx;
    float s2 = 0.f;
    for (int c = threadIdx.x; c < C_DIM; c += blockDim.x) {
        float v = xr[c]; s2 += v * v;
    }
    float S2 = block_reduce(s2, sh, false);
    float inv = rsqrtf(S2 * (1.f / C_DIM) + EPS);
    int f  = row / 1200;
    int rm = row % 1200;
    int hh = rm / 40;
    int ww = rm % 40;
    for (int p = threadIdx.x; p < NH * 64; p += blockDim.x) {
        int n = p >> 6, j = p & 63;
        int pos = (j < 22) ? f : ((j < 43) ? hh : ww);
        float cs = freqs[(pos * 64 + j) * 2 + 0];
        float sn = freqs[(pos * 64 + j) * 2 + 1];
        int c = n * HD + 2 * j;
        float a = xr[c] * inv * w[c];
        float b = xr[c + 1] * inv * w[c + 1];
        float o0 = a * cs - b * sn;
        float o1 = a * sn + b * cs;
        __half h0 = __float2half_rn(o0);
        __half h1 = __float2half_rn(o1);
        long long o = (long long)row * C_DIM + c;
        *reinterpret_cast<ushort2*>(dh + o) = make_ushort2(
            *reinterpret_cast<unsigned short*>(&h0),
            *reinterpret_cast<unsigned short*>(&h1));
    }
}

__global__ void rms_split_kernel(const float* __restrict__ x, int ldx,
                                 const float* __restrict__ w,
                                 unsigned short* __restrict__ dh) {
    __shared__ float sh[32];
    long long row = blockIdx.x;
    const float* xr = x + row * ldx;
    float s2 = 0.f;
    for (int c = threadIdx.x; c < C_DIM; c += blockDim.x) {
        float v = xr[c]; s2 += v * v;
    }
    float S2 = block_reduce(s2, sh, false);
    float inv = rsqrtf(S2 * (1.f / C_DIM) + EPS);
    for (int c = threadIdx.x; c < C_DIM; c += blockDim.x) {
        float v = xr[c] * inv * w[c];
        __half hv = __float2half_rn(v);
        dh[row * C_DIM + c] = *reinterpret_cast<unsigned short*>(&hv);
    }
}

__global__ void conv_h_kernel(const float* __restrict__ src, long long n,
                              unsigned short* __restrict__ dh) {
    long long i = (long long)blockIdx.x * blockDim.x + threadIdx.x;
    if (i < n) {
        __half hv = __float2half_rn(src[i]);
        dh[i] = *reinterpret_cast<unsigned short*>(&hv);
    }
}

// [R, Ccol] fp32 (row stride lds) -> [Ccol, R(ldout)] fp16 HI ONLY
__global__ void transpose_h_kernel(const float* __restrict__ src, int R, int Ccol, int lds,
                                   unsigned short* __restrict__ dh, int ldout) {
    __shared__ float tile[32][33];
    int bx = blockIdx.x, by = blockIdx.y;
    int tx = threadIdx.x, ty = threadIdx.y;  // 32 x 8
    #pragma unroll
    for (int i = 0; i < 4; i++) {
        int r = by * 32 + ty + i * 8;
        tile[ty + i * 8][tx] = src[(long long)r * lds + bx * 32 + tx];
    }
    __syncthreads();
    #pragma unroll
    for (int i = 0; i < 4; i++) {
        int ro = bx * 32 + ty + i * 8;
        int co = by * 32 + tx;
        __half hv = __float2half_rn(tile[tx][ty + i * 8]);
        dh[(long long)ro * ldout + co] = *reinterpret_cast<unsigned short*>(&hv);
    }
}

// batched transpose of 8 CxC weights; grid (48, 48, 8)
__global__ void trh8_kernel(const float* p0, const float* p1, const float* p2, const float* p3,
                            const float* p4, const float* p5, const float* p6, const float* p7,
                            unsigned short* __restrict__ dst) {
    __shared__ float tile[32][33];
    const float* srcs[8] = {p0, p1, p2, p3, p4, p5, p6, p7};
    const float* src = srcs[blockIdx.z];
    unsigned short* dh = dst + (long long)blockIdx.z * C_DIM * C_DIM;
    int bx = blockIdx.x, by = blockIdx.y;
    int tx = threadIdx.x, ty = threadIdx.y;
    #pragma unroll
    for (int i = 0; i < 4; i++) {
        int r = by * 32 + ty + i * 8;
        tile[ty + i * 8][tx] = src[(long long)r * C_DIM + bx * 32 + tx];
    }
    __syncthreads();
    #pragma unroll
    for (int i = 0; i < 4; i++) {
        int ro = bx * 32 + ty + i * 8;
        int co = by * 32 + tx;
        __half hv = __float2half_rn(tile[tx][ty + i * 8]);
        dh[(long long)ro * C_DIM + co] = *reinterpret_cast<unsigned short*>(&hv);
    }
}

// ---------------- common GEMM asm helpers ----------------
static __device__ __forceinline__ uint32_t smem_u32(const void* p) {
    uint32_t r;
    asm("{ .reg .u64 t; cvta.to.shared.u64 t, %1; cvt.u32.u64 %0, t; }" : "=r"(r) : "l"(p));
    return r;
}
static __device__ __forceinline__ void cpa16(uint32_t s, const void* g, uint32_t sz) {
    asm volatile("cp.async.cg.shared.global [%0], [%1], 16, %2;" :: "r"(s), "l"(g), "r"(sz));
}
static __device__ __forceinline__ void cpa_commit() {
    asm volatile("cp.async.commit_group;");
}
static __device__ __forceinline__ void cpa_wait1() {
    asm volatile("cp.async.wait_group 1;");
}
static __device__ __forceinline__ void cpa_wait2() {
    asm volatile("cp.async.wait_group 2;");
}
static __device__ __forceinline__ void ldm_x4(uint32_t* r, uint32_t addr) {
    asm volatile("ldmatrix.sync.aligned.m8n8.x4.shared.b16 {%0,%1,%2,%3}, [%4];"
                 : "=r"(r[0]), "=r"(r[1]), "=r"(r[2]), "=r"(r[3]) : "r"(addr));
}
static __device__ __forceinline__ void mma16816(float* c, const uint32_t* a, uint32_t b0, uint32_t b1) {
    asm volatile("mma.sync.aligned.m16n8k16.row.col.f32.f16.f16.f32 "
                 "{%0,%1,%2,%3}, {%4,%5,%6,%7}, {%8,%9}, {%0,%1,%2,%3};"
                 : "+f"(c[0]), "+f"(c[1]), "+f"(c[2]), "+f"(c[3])
                 : "r"(a[0]), "r"(a[1]), "r"(a[2]), "r"(a[3]), "r"(b0), "r"(b1));
}
static __device__ __forceinline__ uint32_t saddr128(int row, int ch) {
    return (uint32_t)(row * 128 + ((ch ^ (row & 7)) << 4));
}
static __device__ __forceinline__ uint32_t saddr256(int row, int ch) {
    return (uint32_t)(row * 256 + ((ch ^ (row & 7)) << 4));
}

// epilogue helper
static __device__ __forceinline__ void epi_store(
    float v0, float v1, long long o,
    float* Cf, unsigned short* Ch,
    const float* resid, float e0, float e1) {
    if (resid) {
        v0 = resid[o]     + v0 * e0;
        v1 = resid[o + 1] + v1 * e1;
    }
    if (Cf) *reinterpret_cast<float2*>(Cf + o) = make_float2(v0, v1);
    if (Ch) {
        __half h0 = __float2half_rn(v0);
        __half h1 = __float2half_rn(v1);
        *reinterpret_cast<ushort2*>(Ch + o) = make_ushort2(
            *reinterpret_cast<unsigned short*>(&h0),
            *reinterpret_cast<unsigned short*>(&h1));
    }
}

// =====================================================================
// WIDE GEMM (1-product): 128x256x64, warp tile 64x64, 4 stages x 48KB.
// =====================================================================
#define W_STG 49152
#define W_SA 0
#define W_SB 16384
#define W_SMEM (4 * W_STG)

__global__ void __launch_bounds__(256, 1)
hgemmw_kernel(const unsigned short* __restrict__ Ah, int lda,
              const unsigned short* __restrict__ Bh, int ldb,
              float* __restrict__ Cf, unsigned short* __restrict__ Ch, int ldc,
              const float* __restrict__ resid, const float* __restrict__ ecol,
              int M, int N, int K,
              const float* __restrict__ bias, float scale, int act) {
    extern __shared__ char smem[];
    uint32_t sbase = smem_u32(smem);

    int tid = threadIdx.x, lane = tid & 31, warp = tid >> 5;
    int wm = warp & 1, wn = warp >> 1;

    int bm = blockIdx.y * 128;
    int bn = blockIdx.x * 256;
    int mRem = M - bm; if (mRem > 128) mRem = 128;
    int nRem = N - bn; if (nRem > 256) nRem = 256;

    int nch = K >> 6;

    int row0 = tid >> 3, ch0 = tid & 7;
    uint32_t so0 = saddr128(row0, ch0);
    long long gA0 = (long long)(bm + row0) * lda + ch0 * 8;
    long long gB0 = (long long)(bn + row0) * ldb + ch0 * 8;
    uint32_t szA[4], szB[8];
    #pragma unroll
    for (int i = 0; i < 4; i++) szA[i] = (row0 + 32 * i < mRem) ? 16u : 0u;
    #pragma unroll
    for (int i = 0; i < 8; i++) szB[i] = (row0 + 32 * i < nRem) ? 16u : 0u;
    long long ldax = (long long)lda * 32, ldbx = (long long)ldb * 32;

    auto loadStage = [&](int c) {
        uint32_t sb = sbase + (uint32_t)((c & 3) * W_STG);
        long long k0 = (long long)(c << 6);
        #pragma unroll
        for (int i = 0; i < 4; i++)
            cpa16(sb + W_SA + so0 + i * 4096u, Ah + gA0 + i * ldax + k0, szA[i]);
        #pragma unroll
        for (int i = 0; i < 8; i++)
            cpa16(sb + W_SB + so0 + i * 4096u, Bh + gB0 + i * ldbx + k0, szB[i]);
    };

    int frow = lane & 15, fhalf = lane >> 4;
    uint32_t a_rb[4]; int a_x[4];
    #pragma unroll
    for (int mi = 0; mi < 4; mi++) {
        int row = wm * 64 + mi * 16 + frow;
        a_rb[mi] = (uint32_t)(row * 128);
        a_x[mi]  = row & 7;
    }
    uint32_t b_rb[4]; int b_x[4];
    #pragma unroll
    for (int nj = 0; nj < 4; nj++) {
        int row = wn * 64 + nj * 16 + frow;
        b_rb[nj] = (uint32_t)(row * 128);
        b_x[nj]  = row & 7;
    }

    float acc[4][8][4];
    #pragma unroll
    for (int mi = 0; mi < 4; mi++)
        #pragma unroll
        for (int ni = 0; ni < 8; ni++)
            #pragma unroll
            for (int q = 0; q < 4; q++) acc[mi][ni][q] = 0.f;

    #pragma unroll
    for (int p = 0; p < 3; p++) {
        if (p < nch) loadStage(p);
        cpa_commit();
    }

    for (int c = 0; c < nch; c++) {
        cpa_wait2();
        __syncthreads();
        uint32_t sb = sbase + (uint32_t)((c & 3) * W_STG);

        #pragma unroll
        for (int k16 = 0; k16 < 4; k16++) {
            int chl = k16 * 2 + fhalf;
            uint32_t bH[4][4];
            #pragma unroll
            for (int nj = 0; nj < 4; nj++) {
                uint32_t off = b_rb[nj] + (uint32_t)(((chl ^ b_x[nj])) << 4);
                ldm_x4(bH[nj], sb + W_SB + off);
            }
            #pragma unroll
            for (int mi = 0; mi < 4; mi++) {
                uint32_t aH[4];
                uint32_t off = a_rb[mi] + (uint32_t)(((chl ^ a_x[mi])) << 4);
                ldm_x4(aH, sb + W_SA + off);
                #pragma unroll
                for (int nj = 0; nj < 4; nj++) {
                    mma16816(acc[mi][nj*2+0], aH, bH[nj][0], bH[nj][2]);
                    mma16816(acc[mi][nj*2+1], aH, bH[nj][1], bH[nj][3]);
                }
            }
        }
        if (c + 3 < nch) loadStage(c + 3);
        cpa_commit();
    }

    int erow = lane >> 2;
    int ecolL = (lane & 3) * 2;
    #pragma unroll
    for (int mi = 0; mi < 4; mi++) {
        #pragma unroll
        for (int ni = 0; ni < 8; ni++) {
            int gn = bn + wn * 64 + (ni >> 1) * 16 + (ni & 1) * 8 + ecolL;
            if (gn >= N) continue;
            float b0 = 0.f, b1 = 0.f;
            if (bias) { b0 = bias[gn]; b1 = bias[gn + 1]; }
            float e0 = 1.f, e1 = 1.f;
            if (ecol) { e0 = ecol[gn]; e1 = ecol[gn + 1]; }
            float* cc = acc[mi][ni];
            #pragma unroll
            for (int half = 0; half < 2; half++) {
                int gm = bm + wm * 64 + mi * 16 + erow + half * 8;
                if (gm >= M) continue;
                float v0 = cc[half * 2 + 0] * scale + b0;
                float v1 = cc[half * 2 + 1] * scale + b1;
                if (act == 1) { v0 = gelu_tanh(v0); v1 = gelu_tanh(v1); }
                epi_store(v0, v1, (long long)gm * ldc + gn, Cf, Ch, resid, e0, e1);
            }
        }
    }
}

// =====================================================================
// NARROW GEMM (1-product): 128x128x64, 3 stages x 32KB, 2 CTAs/SM.
// =====================================================================
#define N_STG 32768
#define N_SA 0
#define N_SB 16384
#define HG_SMEM (3 * N_STG)

__global__ void __launch_bounds__(256, 2)
hgemmn_kernel(const unsigned short* __restrict__ Ah, int lda,
              const unsigned short* __restrict__ Bh, int ldb,
              float* __restrict__ Cf, unsigned short* __restrict__ Ch, int ldc,
              const float* __restrict__ resid, const float* __restrict__ ecol,
              int M, int N, int K,
              const float* __restrict__ bias, float scale, int act) {
    extern __shared__ char smem[];
    uint32_t sbase = smem_u32(smem);

    int tid = threadIdx.x, lane = tid & 31, warp = tid >> 5;
    int wm = warp & 1, wn = warp >> 1;   // warp tile 64x32

    int bm = blockIdx.y * 128;
    int bn = blockIdx.x * 128;
    int mRem = M - bm; if (mRem > 128) mRem = 128;
    int nRem = N - bn; if (nRem > 128) nRem = 128;

    int nch = K >> 6;

    int row0 = tid >> 3, ch0 = tid & 7;
    uint32_t so0 = saddr128(row0, ch0);
    long long gA0 = (long long)(bm + row0) * lda + ch0 * 8;
    long long gB0 = (long long)(bn + row0) * ldb + ch0 * 8;
    uint32_t szA[4], szB[4];
    #pragma unroll
    for (int i = 0; i < 4; i++) {
        szA[i] = (row0 + 32 * i < mRem) ? 16u : 0u;
        szB[i] = (row0 + 32 * i < nRem) ? 16u : 0u;
    }
    long long ldax = (long long)lda * 32, ldbx = (long long)ldb * 32;

    auto loadStage = [&](int c) {
        uint32_t sb = sbase + (uint32_t)((c % 3) * N_STG);
        long long k0 = (long long)(c << 6);
        #pragma unroll
        for (int i = 0; i < 4; i++) {
            cpa16(sb + N_SA + so0 + i * 4096u, Ah + gA0 + i * ldax + k0, szA[i]);
            cpa16(sb + N_SB + so0 + i * 4096u, Bh + gB0 + i * ldbx + k0, szB[i]);
        }
    };

    int frow = lane & 15, fhalf = lane >> 4;
    uint32_t a_rb[4]; int a_x[4];
    #pragma unroll
    for (int mi = 0; mi < 4; mi++) {
        int row = wm * 64 + mi * 16 + frow;
        a_rb[mi] = (uint32_t)(row * 128);
        a_x[mi]  = row & 7;
    }
    uint32_t b_rb[2]; int b_x[2];
    #pragma unroll
    for (int nj = 0; nj < 2; nj++) {
        int row = wn * 32 + nj * 16 + frow;
        b_rb[nj] = (uint32_t)(row * 128);
        b_x[nj]  = row & 7;
    }

    float acc[4][4][4];
    #pragma unroll
    for (int mi = 0; mi < 4; mi++)
        #pragma unroll
        for (int ni = 0; ni < 4; ni++)
            #pragma unroll
            for (int q = 0; q < 4; q++) acc[mi][ni][q] = 0.f;

    loadStage(0); cpa_commit();
    if (nch > 1) loadStage(1);
    cpa_commit();

    for (int c = 0; c < nch; c++) {
        cpa_wait1();
        __syncthreads();
        uint32_t sb = sbase + (uint32_t)((c % 3) * N_STG);

        #pragma unroll
        for (int k16 = 0; k16 < 4; k16++) {
            int chl = k16 * 2 + fhalf;
            uint32_t bH[2][4];
            #pragma unroll
            for (int nj = 0; nj < 2; nj++) {
                uint32_t off = b_rb[nj] + (uint32_t)(((chl ^ b_x[nj])) << 4);
                ldm_x4(bH[nj], sb + N_SB + off);
            }
            #pragma unroll
            for (int mi = 0; mi < 4; mi++) {
                uint32_t aH[4];
                uint32_t off = a_rb[mi] + (uint32_t)(((chl ^ a_x[mi])) << 4);
                ldm_x4(aH, sb + N_SA + off);
                #pragma unroll
                for (int nj = 0; nj < 2; nj++) {
                    mma16816(acc[mi][nj*2+0], aH, bH[nj][0], bH[nj][2]);
                    mma16816(acc[mi][nj*2+1], aH, bH[nj][1], bH[nj][3]);
                }
            }
        }
        if (c + 2 < nch) loadStage(c + 2);
        cpa_commit();
    }

    int erow = lane >> 2;
    int ecolL = (lane & 3) * 2;
    #pragma unroll
    for (int mi = 0; mi < 4; mi++) {
        #pragma unroll
        for (int ni = 0; ni < 4; ni++) {
            int gn = bn + wn * 32 + ni * 8 + ecolL;
            if (gn >= N) continue;
            float b0 = 0.f, b1 = 0.f;
            if (bias) { b0 = bias[gn]; b1 = bias[gn + 1]; }
            float e0 = 1.f, e1 = 1.f;
            if (ecol) { e0 = ecol[gn]; e1 = ecol[gn + 1]; }
            float* cc = acc[mi][ni];
            #pragma unroll
            for (int half = 0; half < 2; half++) {
                int gm = bm + wm * 64 + mi * 16 + erow + half * 8;
                if (gm >= M) continue;
                float v0 = cc[half * 2 + 0] * scale + b0;
                float v1 = cc[half * 2 + 1] * scale + b1;
                if (act == 1) { v0 = gelu_tanh(v0); v1 = gelu_tanh(v1); }
                epi_store(v0, v1, (long long)gm * ldc + gn, Cf, Ch, resid, e0, e1);
            }
        }
    }
}

// =====================================================================
// FUSED ATTENTION (flash-style), q hi-only, exp2-domain softmax.
//   ascale passed PRE-MULTIPLIED by log2(e). Grid (NH, ceil(L_Q/128)).
// =====================================================================
#define FL_QH 0
#define FL_KP0 32768
#define FL_KP1 65536
#define FL_V0 98304
#define FL_V1 131072
#define FL_SMEM 163840

__global__ void __launch_bounds__(256, 1)
flash_kernel(const unsigned short* __restrict__ qh,
             const unsigned short* __restrict__ kh, const unsigned short* __restrict__ vt,
             unsigned short* __restrict__ yh,
             float ascale2, int lkv, int ldv) {
    extern __shared__ char smem[];
    uint32_t sb = smem_u32(smem);
    int tid = threadIdx.x, lane = tid & 31, warp = tid >> 5;
    int head = blockIdx.x;
    int q0 = blockIdx.y * 128;

    const unsigned short* kbase = kh + head * HD;
    const unsigned short* vbase = vt + (long long)(head * HD) * ldv;

    auto loadQ = [&]() {
        #pragma unroll
        for (int i = 0; i < 8; i++) {
            int idx = tid + i * 256;
            int row = idx >> 4, ch = idx & 15;
            uint32_t sz = (q0 + row < L_Q) ? 16u : 0u;
            long long g = (long long)(q0 + row) * C_DIM + head * HD + ch * 8;
            cpa16(sb + FL_QH + saddr256(row, ch), qh + g, sz);
        }
    };
    auto loadKV = [&](int c) {
        uint32_t kb = sb + ((c & 1) ? FL_KP1 : FL_KP0);
        uint32_t vb = sb + ((c & 1) ? FL_V1 : FL_V0);
        int kv0 = c * 128;
        #pragma unroll
        for (int i = 0; i < 8; i++) {
            int idx = tid + i * 256;
            int row = idx >> 4, ch = idx & 15;
            uint32_t so = saddr256(row, ch);
            uint32_t sz = (kv0 + row < lkv) ? 16u : 0u;
            cpa16(kb + so, kbase + (long long)(kv0 + row) * C_DIM + ch * 8, sz);
            cpa16(vb + so, vbase + (long long)row * ldv + kv0 + ch * 8, 16u);
        }
    };

    int frow = lane & 15, fhalf = lane >> 4;
    int fx = frow & 7;
    uint32_t a_rb = (uint32_t)((warp * 16 + frow) * 256);
    uint32_t b_rb[8];
    #pragma unroll
    for (int nj = 0; nj < 8; nj++) b_rb[nj] = (uint32_t)((nj * 16 + frow) * 256);

    float m[2] = {-INFINITY, -INFINITY};
    float l[2] = {0.f, 0.f};
    float o[8][2][4];
    #pragma unroll
    for (int dj = 0; dj < 8; dj++)
        #pragma unroll
        for (int t = 0; t < 2; t++)
            #pragma unroll
            for (int q = 0; q < 4; q++) o[dj][t][q] = 0.f;

    loadQ(); loadKV(0); cpa_commit();
    const int nch = (lkv + 127) / 128;
    if (nch > 1) loadKV(1);
    cpa_commit();

    for (int c = 0; c < nch; c++) {
        cpa_wait1();
        __syncthreads();
        uint32_t kb = sb + ((c & 1) ? FL_KP1 : FL_KP0);
        uint32_t vb = sb + ((c & 1) ? FL_V1 : FL_V0);
        int kvRem = lkv - c * 128; if (kvRem > 128) kvRem = 128;

        float sacc[8][2][4];
        #pragma unroll
        for (int nj = 0; nj < 8; nj++)
            #pragma unroll
            for (int t = 0; t < 2; t++)
                #pragma unroll
                for (int q = 0; q < 4; q++) sacc[nj][t][q] = 0.f;

        #pragma unroll
        for (int kk = 0; kk < 8; kk++) {
            int chl = kk * 2 + fhalf;
            uint32_t aH[4];
            ldm_x4(aH, sb + FL_QH + a_rb + (uint32_t)((chl ^ fx) << 4));
            #pragma unroll
            for (int nj = 0; nj < 8; nj++) {
                uint32_t bH[4];
                ldm_x4(bH, kb + b_rb[nj] + (uint32_t)((chl ^ fx) << 4));
                mma16816(sacc[nj][0], aH, bH[0], bH[2]);
                mma16816(sacc[nj][1], aH, bH[1], bH[3]);
            }
        }
        __syncthreads();

        int ec = (lane & 3) * 2;
        #pragma unroll
        for (int half = 0; half < 2; half++) {
            float mc = -INFINITY;
            #pragma unroll
            for (int nj = 0; nj < 8; nj++)
                #pragma unroll
                for (int t = 0; t < 2; t++)
                    #pragma unroll
                    for (int j = 0; j < 2; j++) {
                        int col = nj * 16 + t * 8 + ec + j;
                        float v = sacc[nj][t][half * 2 + j] * ascale2;  // log2 domain
                        sacc[nj][t][half * 2 + j] = v;
                        if (col < kvRem) mc = fmaxf(mc, v);
                    }
            mc = fmaxf(mc, __shfl_xor_sync(0xffffffffu, mc, 1));
            mc = fmaxf(mc, __shfl_xor_sync(0xffffffffu, mc, 2));
            float mn = fmaxf(m[half], mc);
            float corr = fexp2(m[half] - mn);
            m[half] = mn;
            float ls = 0.f;
            #pragma unroll
            for (int nj = 0; nj < 8; nj++)
                #pragma unroll
                for (int t = 0; t < 2; t++)
                    #pragma unroll
                    for (int j = 0; j < 2; j++) {
                        int col = nj * 16 + t * 8 + ec + j;
                        float p = (col < kvRem)
                                ? fexp2(sacc[nj][t][half * 2 + j] - mn) : 0.f;
                        sacc[nj][t][half * 2 + j] = p;
                        ls += p;
                    }
            l[half] = l[half] * corr + ls;
            #pragma unroll
            for (int dj = 0; dj < 8; dj++)
                #pragma unroll
                for (int t = 0; t < 2; t++)
                    #pragma unroll
                    for (int j = 0; j < 2; j++)
                        o[dj][t][half * 2 + j] *= corr;
        }

        #pragma unroll
        for (int half = 0; half < 2; half++) {
            int row = warp * 16 + (lane >> 2) + half * 8;
            #pragma unroll
            for (int nj = 0; nj < 8; nj++)
                #pragma unroll
                for (int t = 0; t < 2; t++) {
                    int col = nj * 16 + t * 8 + ec;
                    __half p0 = __float2half_rn(sacc[nj][t][half * 2 + 0]);
                    __half p1 = __float2half_rn(sacc[nj][t][half * 2 + 1]);
                    uint32_t addr = kb + (uint32_t)(row * 256 +
                                    (((col >> 3) ^ (row & 7)) << 4) + (col & 7) * 2);
                    uint32_t pk = (uint32_t)*reinterpret_cast<unsigned short*>(&p0)
                                | ((uint32_t)*reinterpret_cast<unsigned short*>(&p1) << 16);
                    asm volatile("st.shared.u32 [%0], %1;" :: "r"(addr), "r"(pk));
                }
        }
        __syncwarp();

        #pragma unroll
        for (int kk = 0; kk < 8; kk++) {
            int chl = kk * 2 + fhalf;
            uint32_t aP[4];
            ldm_x4(aP, kb + a_rb + (uint32_t)((chl ^ fx) << 4));
            #pragma unroll
            for (int dj = 0; dj < 8; dj++) {
                uint32_t bV[4];
                ldm_x4(bV, vb + b_rb[dj] + (uint32_t)((chl ^ fx) << 4));
                mma16816(o[dj][0], aP, bV[0], bV[2]);
                mma16816(o[dj][1], aP, bV[1], bV[3]);
            }
        }
        __syncthreads();
        if (c + 2 < nch) loadKV(c + 2);
        cpa_commit();
    }

    int ec = (lane & 3) * 2;
    #pragma unroll
    for (int half = 0; half < 2; half++) {
        float ls = l[half];
        ls += __shfl_xor_sync(0xffffffffu, ls, 1);
        ls += __shfl_xor_sync(0xffffffffu, ls, 2);
        float inv = 1.f / ls;
        int gm = q0 + warp * 16 + (lane >> 2) + half * 8;
        if (gm >= L_Q) continue;
        #pragma unroll
        for (int dj = 0; dj < 8; dj++)
            #pragma unroll
            for (int t = 0; t < 2; t++) {
                int gd = head * HD + dj * 16 + t * 8 + ec;
                float v0 = o[dj][t][half * 2 + 0] * inv;
                float v1 = o[dj][t][half * 2 + 1] * inv;
                __half h0 = __float2half_rn(v0);
                __half h1 = __float2half_rn(v1);
                long long off = (long long)gm * C_DIM + gd;
                *reinterpret_cast<ushort2*>(yh + off) = make_ushort2(
                    *reinterpret_cast<unsigned short*>(&h0),
                    *reinterpret_cast<unsigned short*>(&h1));
            }
    }
}

// ---------------- host ----------------
static void hgw(const unsigned short* Ah, int lda, const unsigned short* Bh, int ldb,
                float* Cf, unsigned short* Ch, int ldc,
                const float* resid, const float* ecol,
                int M, int N, int K, const float* bias, float scale, int act) {
    dim3 grid((N + 255) / 256, (M + 127) / 128);
    hgemmw_kernel<<<grid, 256, W_SMEM>>>(Ah, lda, Bh, ldb, Cf, Ch, ldc,
                                         resid, ecol, M, N, K, bias, scale, act);
}

static void hgn(const unsigned short* Ah, int lda, const unsigned short* Bh, int ldb,
                float* Cf, unsigned short* Ch, int ldc,
                const float* resid, const float* ecol,
                int M, int N, int K, const float* bias, float scale, int act) {
    dim3 grid((N + 127) / 128, (M + 127) / 128);
    hgemmn_kernel<<<grid, 256, HG_SMEM>>>(Ah, lda, Bh, ldb, Cf, Ch, ldc,
                                          resid, ecol, M, N, K, bias, scale, act);
}

static void trh(const float* src, int R, int Ccol, int lds, unsigned short* dh, int ldout) {
    dim3 grid(Ccol / 32, R / 32);
    transpose_h_kernel<<<grid, dim3(32, 8)>>>(src, R, Ccol, lds, dh, ldout);
}

extern "C" void kernel_launch(void* const* d_in, const int* in_sizes, int n_in,
                              void* d_out, int out_size) {
    const float* x        = (const float*)d_in[0];
    const float* e        = (const float*)d_in[1];
    const float* context  = (const float*)d_in[2];
    const float* freqs    = (const float*)d_in[3];
    const float* modulation = (const float*)d_in[7];
    const float* sa_q_w = (const float*)d_in[8];
    const float* sa_q_b = (const float*)d_in[9];
    const float* sa_k_w = (const float*)d_in[10];
    const float* sa_k_b = (const float*)d_in[11];
    const float* sa_v_w = (const float*)d_in[12];
    const float* sa_v_b = (const float*)d_in[13];
    const float* sa_o_w = (const float*)d_in[14];
    const float* sa_o_b = (const float*)d_in[15];
    const float* sa_nq_w = (const float*)d_in[16];
    const float* sa_nk_w = (const float*)d_in[17];
    const float* ca_q_w = (const float*)d_in[18];
    const float* ca_q_b = (const float*)d_in[19];
    const float* ca_k_w = (const float*)d_in[20];
    const float* ca_k_b = (const float*)d_in[21];
    const float* ca_v_w = (const float*)d_in[22];
    const float* ca_v_b = (const float*)d_in[23];
    const float* ca_o_w = (const float*)d_in[24];
    const float* ca_o_b = (const float*)d_in[25];
    const float* ca_nq_w = (const float*)d_in[26];
    const float* ca_nk_w = (const float*)d_in[27];
    const float* ffn_w1 = (const float*)d_in[28];
    const float* ffn_b1 = (const float*)d_in[29];
    const float* ffn_w2 = (const float*)d_in[30];
    const float* ffn_b2 = (const float*)d_in[31];
    float* out = (float*)d_out;

    cudaFuncSetAttribute(hgemmw_kernel,
                         cudaFuncAttributeMaxDynamicSharedMemorySize, W_SMEM);
    cudaFuncSetAttribute(hgemmn_kernel,
                         cudaFuncAttributeMaxDynamicSharedMemorySize, HG_SMEM);
    cudaFuncSetAttribute(flash_kernel,
                         cudaFuncAttributeMaxDynamicSharedMemorySize, FL_SMEM);

    float *em, *q, *s, *b3;
    unsigned short *hh, *qh, *kh, *vth, *yh, *oh, *cxh, *ffh, *wA, *wF;
    cudaGetSymbolAddress((void**)&em, g_em);
    cudaGetSymbolAddress((void**)&q,  g_q);
    cudaGetSymbolAddress((void**)&s,  g_s);
    cudaGetSymbolAddress((void**)&b3, g_b3);
    cudaGetSymbolAddress((void**)&hh, g_hh);
    cudaGetSymbolAddress((void**)&qh, g_qh);
    cudaGetSymbolAddress((void**)&kh, g_kh);
    cudaGetSymbolAddress((void**)&vth, g_vth);
    cudaGetSymbolAddress((void**)&yh, g_yh);
    cudaGetSymbolAddress((void**)&oh, g_oh);
    cudaGetSymbolAddress((void**)&cxh, g_cxh);
    cudaGetSymbolAddress((void**)&ffh, g_ffh);
    cudaGetSymbolAddress((void**)&wA, g_wA);
    cudaGetSymbolAddress((void**)&wF, g_wF);

    // 1/sqrt(128) * log2(e): softmax runs in exp2 domain
    const float ascale2 = 0.08838834764831845f * 1.4426950408889634f;
    const long long CC = (long long)C_DIM * C_DIM;

    em_kernel<<<(6 * C_DIM + 255) / 256, 256>>>(e, modulation, em);
    trh8_kernel<<<dim3(48, 48, 8), dim3(32, 8)>>>(
        sa_q_w, sa_k_w, sa_v_w, sa_o_w, ca_q_w, ca_k_w, ca_v_w, ca_o_w, wA);
    trh(ffn_w1, C_DIM, FF_DIM, FF_DIM, wF, C_DIM);
    trh(ffn_w2, FF_DIM, C_DIM, C_DIM, wF + (long long)C_DIM * FF_DIM, FF_DIM);
    pack3_kernel<<<(3 * C_DIM + 255) / 256, 256>>>(sa_q_b, sa_k_b, sa_v_b, b3);

    // ================= self attention =================
    ln_mod_split_kernel<<<L_Q, 256>>>(x, em + 0 * C_DIM, em + 1 * C_DIM, hh);
    float* qkv = s;   // [2400, 4608] fp32
    hgw(hh, C_DIM, wA, C_DIM, qkv, nullptr, 3 * C_DIM,
        nullptr, nullptr, L_Q, 3 * C_DIM, C_DIM, b3, 1.f, 0);
    rms_rope_split_kernel<<<L_Q, 256>>>(qkv + 0 * C_DIM, 3 * C_DIM, sa_nq_w, freqs, qh);
    rms_rope_split_kernel<<<L_Q, 256>>>(qkv + 1 * C_DIM, 3 * C_DIM, sa_nk_w, freqs, kh);
    trh(qkv + 2 * C_DIM, L_Q, C_DIM, 3 * C_DIM, vth, L_PAD);
    zero_pad_kernel<<<(C_DIM * 32 + 255) / 256, 256>>>(vth);
    flash_kernel<<<dim3(NH, (L_Q + 127) / 128), 256, FL_SMEM>>>(
        qh, kh, vth, yh, ascale2, L_Q, L_PAD);
    hgn(yh, C_DIM, wA + 3 * CC, C_DIM, out, oh, C_DIM,
        x, em + 2 * C_DIM, L_Q, C_DIM, C_DIM, sa_o_b, 1.f, 0);

    // ================= cross attention =================
    hgn(oh, C_DIM, wA + 4 * CC, C_DIM, q, nullptr, C_DIM,
        nullptr, nullptr, L_Q, C_DIM, C_DIM, ca_q_b, 1.f, 0);
    rms_split_kernel<<<L_Q, 256>>>(q, C_DIM, ca_nq_w, qh);
    conv_h_kernel<<<(int)(((long long)L_KV * C_DIM + 255) / 256), 256>>>(
        context, (long long)L_KV * C_DIM, cxh);
    pack2_kernel<<<(2 * C_DIM + 255) / 256, 256>>>(ca_k_b, ca_v_b, b3);
    float* kvbuf = s;   // [512, 3072] fp32
    hgn(cxh, C_DIM, wA + 5 * CC, C_DIM, kvbuf, nullptr, 2 * C_DIM,
        nullptr, nullptr, L_KV, 2 * C_DIM, C_DIM, b3, 1.f, 0);
    rms_split_kernel<<<L_KV, 256>>>(kvbuf + 0 * C_DIM, 2 * C_DIM, ca_nk_w, kh);
    trh(kvbuf + 1 * C_DIM, L_KV, C_DIM, 2 * C_DIM, vth, L_KV);
    flash_kernel<<<dim3(NH, (L_Q + 127) / 128), 256, FL_SMEM>>>(
        qh, kh, vth, yh, ascale2, L_KV, L_KV);
    hgn(yh, C_DIM, wA + 7 * CC, C_DIM, out, nullptr, C_DIM,
        out, nullptr, L_Q, C_DIM, C_DIM, ca_o_b, 1.f, 0);

    // ================= FFN =================
    ln_mod_split_kernel<<<L_Q, 256>>>(out, em + 3 * C_DIM, em + 4 * C_DIM, hh);
    hgw(hh, C_DIM, wF, C_DIM, nullptr, ffh, FF_DIM,
        nullptr, nullptr, L_Q, FF_DIM, C_DIM, ffn_b1, 1.f, 1);   // + GELU
    hgn(ffh, FF_DIM, wF + (long long)C_DIM * FF_DIM, FF_DIM, out, nullptr, C_DIM,
        out, em + 5 * C_DIM, L_Q, C_DIM, FF_DIM, ffn_b2, 1.f, 0);
}